// round 2
// baseline (speedup 1.0000x reference)
#include <cuda_runtime.h>
#include <math.h>

// Problem constants
#define Bn   32
#define C1n  256
#define CHn  128
#define Hn   80
#define Wn   80
#define HWn  6400
#define NRn  3

// ---------------------------------------------------------------------------
// Scratch (device globals: allocation-free per harness rules)
// ---------------------------------------------------------------------------
__device__ float g_t  [Bn * C1n * HWn];   // t = silu(conv1(x)) : [B,256,HW] (a = ch 0..127, feat = ch 128..255)
__device__ float g_moe[Bn * CHn * HWn];   // moe_out            : [B,128,HW]
__device__ float g_pooled[Bn * CHn];
__device__ int   g_eidx[Bn];
__device__ float g_egate[Bn];

__device__ __forceinline__ float silu_f(float v) {
    return v * (1.0f / (1.0f + __expf(-v)));
}

// ---------------------------------------------------------------------------
// Kernel 1/5: 1x1 conv (GEMM) + bias + SiLU
//   out[b, oc, p] = silu( sum_ic w[oc,ic] * in[b, ic, p] + bias[oc] )
// Tile: 128 px x 128 oc per block, 256 threads, each thread 8 px x 8 oc.
// FROM_CAT: input channels 0..255 from g_t, 256..383 from g_moe (K=384).
// WRITE_T : output goes to g_t instead of the outp param.
// ---------------------------------------------------------------------------
template<int KVAL, bool FROM_CAT, bool WRITE_T>
__global__ __launch_bounds__(256) void conv1x1_silu_k(
    const float* __restrict__ xin,     // used when !FROM_CAT : [B,256,HW]
    const float* __restrict__ w,       // [256, KVAL]
    const float* __restrict__ bias,    // [256]
    float* __restrict__ outp)          // used when !WRITE_T
{
    __shared__ float xs [8][128];
    __shared__ float wsm[8][128];

    const int b   = blockIdx.z;
    const int ocB = blockIdx.y * 128;
    const int p0  = blockIdx.x * 128;
    const int tid = threadIdx.x;
    const int pxs = tid & 15;   // pixel strip 0..15 (8 px each)
    const int ocg = tid >> 4;   // oc group 0..15 (8 oc each)

    float acc[8][8];
#pragma unroll
    for (int i = 0; i < 8; ++i)
#pragma unroll
        for (int j = 0; j < 8; ++j) acc[i][j] = 0.0f;

    const int li_c  = tid >> 5;        // 0..7  : channel within chunk
    const int li_f  = tid & 31;        // float4 index within 128-px row
    const int wi_oc = tid >> 1;        // 0..127
    const int wi_i4 = (tid & 1) * 4;

    for (int ic0 = 0; ic0 < KVAL; ic0 += 8) {
        // load 8 x 128 input pixels
        const int c = ic0 + li_c;
        const float* srow;
        if (FROM_CAT) {
            srow = (c < 256) ? (g_t   + ((size_t)b * 256 + c)        * HWn)
                             : (g_moe + ((size_t)b * 128 + (c - 256)) * HWn);
        } else {
            srow = xin + ((size_t)b * 256 + c) * HWn;
        }
        float4 xv = *(const float4*)(srow + p0 + li_f * 4);
        *(float4*)(&xs[li_c][li_f * 4]) = xv;

        // load 8 x 128 weights (transposed into [ic][oc])
        float4 wv = *(const float4*)(w + (size_t)(ocB + wi_oc) * KVAL + ic0 + wi_i4);
        wsm[wi_i4 + 0][wi_oc] = wv.x;
        wsm[wi_i4 + 1][wi_oc] = wv.y;
        wsm[wi_i4 + 2][wi_oc] = wv.z;
        wsm[wi_i4 + 3][wi_oc] = wv.w;
        __syncthreads();

#pragma unroll
        for (int ic = 0; ic < 8; ++ic) {
            float xr[8], wr_[8];
            *(float4*)&xr [0] = *(const float4*)&xs [ic][pxs * 8];
            *(float4*)&xr [4] = *(const float4*)&xs [ic][pxs * 8 + 4];
            *(float4*)&wr_[0] = *(const float4*)&wsm[ic][ocg * 8];
            *(float4*)&wr_[4] = *(const float4*)&wsm[ic][ocg * 8 + 4];
#pragma unroll
            for (int i = 0; i < 8; ++i)
#pragma unroll
                for (int j = 0; j < 8; ++j)
                    acc[i][j] += wr_[i] * xr[j];
        }
        __syncthreads();
    }

    float* dstbase = WRITE_T ? g_t : outp;
#pragma unroll
    for (int i = 0; i < 8; ++i) {
        const int oc = ocB + ocg * 8 + i;
        const float bi = bias[oc];
        float* orow = dstbase + ((size_t)b * 256 + oc) * HWn + p0 + pxs * 8;
        float4 v0, v1;
        v0.x = silu_f(acc[i][0] + bi);
        v0.y = silu_f(acc[i][1] + bi);
        v0.z = silu_f(acc[i][2] + bi);
        v0.w = silu_f(acc[i][3] + bi);
        v1.x = silu_f(acc[i][4] + bi);
        v1.y = silu_f(acc[i][5] + bi);
        v1.z = silu_f(acc[i][6] + bi);
        v1.w = silu_f(acc[i][7] + bi);
        *(float4*)(orow)     = v0;
        *(float4*)(orow + 4) = v1;
    }
}

// ---------------------------------------------------------------------------
// Kernel 2: global average pool of feat (= g_t channels 128..255) -> g_pooled
// ---------------------------------------------------------------------------
__global__ __launch_bounds__(256) void pool_k()
{
    const int c = blockIdx.x;   // 0..127
    const int b = blockIdx.y;   // 0..31
    const float* row = g_t + ((size_t)b * 256 + 128 + c) * HWn;
    float sum = 0.0f;
    for (int i = threadIdx.x; i < HWn / 4; i += 256) {
        float4 v = ((const float4*)row)[i];
        sum += v.x + v.y + v.z + v.w;
    }
    __shared__ float sred[8];
#pragma unroll
    for (int off = 16; off; off >>= 1)
        sum += __shfl_down_sync(0xffffffffu, sum, off);
    if ((threadIdx.x & 31) == 0) sred[threadIdx.x >> 5] = sum;
    __syncthreads();
    if (threadIdx.x < 8) {
        float v = sred[threadIdx.x];
#pragma unroll
        for (int off = 4; off; off >>= 1)
            v += __shfl_down_sync(0xffu, v, off);
        if (threadIdx.x == 0)
            g_pooled[b * 128 + c] = v * (1.0f / (float)HWn);
    }
}

// ---------------------------------------------------------------------------
// Kernel 3: routing (softmax over 3 logits, top-1) -> g_eidx, g_egate
// ---------------------------------------------------------------------------
__global__ void route_k(const float* __restrict__ wr, const float* __restrict__ br)
{
    const int b = threadIdx.x;   // 32 threads
    if (b >= Bn) return;
    float lg[NRn];
#pragma unroll
    for (int e = 0; e < NRn; ++e) lg[e] = br[e];
    for (int c = 0; c < CHn; ++c) {
        const float p = g_pooled[b * 128 + c];
        lg[0] += p * wr[c * NRn + 0];
        lg[1] += p * wr[c * NRn + 1];
        lg[2] += p * wr[c * NRn + 2];
    }
    int best = 0;
    float m = lg[0];
    if (lg[1] > m) { m = lg[1]; best = 1; }   // strict > keeps lowest index on ties (lax.top_k)
    if (lg[2] > m) { m = lg[2]; best = 2; }
    const float s = expf(lg[0] - m) + expf(lg[1] - m) + expf(lg[2] - m);
    g_eidx[b]  = best;
    g_egate[b] = 1.0f / s;   // = softmax(lg)[best]
}

// ---------------------------------------------------------------------------
// Kernel 4: fused 3x3 convs:
//   moe[b,oc] = silu(conv(feat, ws)+bs) + gate[b]*silu(conv(feat, we[eidx[b]])+be[eidx[b]])
// Tile: 40(W) x 16(H) spatial x 8 oc (per conv), 160 threads.
// Each thread: 4-px W-strip x 8 oc x 2 convs = 64 accumulators.
// ---------------------------------------------------------------------------
__global__ __launch_bounds__(160) void conv3x3_moe_k(
    const float* __restrict__ ws, const float* __restrict__ bs,
    const float* __restrict__ we, const float* __restrict__ be)
{
    __shared__ float sIn[8][18][43];        // ic chunk x (16+2) rows x (40+2) cols (padded to 43)
    __shared__ float sWS[8][72];            // [oc][ic*9+tap]
    __shared__ float sWE[8][72];

    const int b   = blockIdx.z;
    const int ocg = blockIdx.y;             // 0..15
    const int bx  = blockIdx.x;             // 0..9
    const int x0  = (bx & 1) * 40;
    const int y0  = (bx >> 1) * 16;
    const int tid = threadIdx.x;
    const int r   = tid / 10;               // 0..15
    const int s   = tid % 10;               // 0..9  (cols x0+4s .. +3)

    const int   e    = g_eidx[b];
    const float gate = g_egate[b];
    const float* feat = g_t + ((size_t)b * 256 + 128) * HWn;
    const float* wE   = we + (size_t)e * CHn * CHn * 9;
    const float* bE   = be + e * CHn;

    float accS[8][4], accE[8][4];
#pragma unroll
    for (int o = 0; o < 8; ++o)
#pragma unroll
        for (int p = 0; p < 4; ++p) { accS[o][p] = 0.0f; accE[o][p] = 0.0f; }

    for (int ic0 = 0; ic0 < CHn; ic0 += 8) {
        // ---- load input tile (with zero halo) ----
        for (int j = tid; j < 18 * 42; j += 160) {
            const int rr = j / 42, cc = j % 42;
            const int gy = y0 - 1 + rr, gx = x0 - 1 + cc;
            const bool ok = ((unsigned)gy < (unsigned)Hn) && ((unsigned)gx < (unsigned)Wn);
            const int  gofs = gy * Wn + gx;
#pragma unroll
            for (int i = 0; i < 8; ++i) {
                float v = 0.0f;
                if (ok) v = feat[(size_t)(ic0 + i) * HWn + gofs];
                sIn[i][rr][cc] = v;
            }
        }
        // ---- load weight chunk (72 contiguous floats per oc) ----
        for (int j = tid; j < 8 * 72; j += 160) {
            const int oc = j / 72, rr = j % 72;
            sWS[oc][rr] = ws[(size_t)(ocg * 8 + oc) * (CHn * 9) + ic0 * 9 + rr];
            sWE[oc][rr] = wE[(size_t)(ocg * 8 + oc) * (CHn * 9) + ic0 * 9 + rr];
        }
        __syncthreads();

        for (int ic = 0; ic < 8; ++ic) {
#pragma unroll
            for (int ky = 0; ky < 3; ++ky) {
                float in6[6];
#pragma unroll
                for (int j = 0; j < 6; ++j) in6[j] = sIn[ic][r + ky][4 * s + j];
#pragma unroll
                for (int kx = 0; kx < 3; ++kx) {
                    float wS8[8], wE8[8];
#pragma unroll
                    for (int o = 0; o < 8; ++o) {
                        wS8[o] = sWS[o][ic * 9 + ky * 3 + kx];
                        wE8[o] = sWE[o][ic * 9 + ky * 3 + kx];
                    }
#pragma unroll
                    for (int o = 0; o < 8; ++o)
#pragma unroll
                        for (int px = 0; px < 4; ++px) {
                            accS[o][px] += in6[px + kx] * wS8[o];
                            accE[o][px] += in6[px + kx] * wE8[o];
                        }
                }
            }
        }
        __syncthreads();
    }

#pragma unroll
    for (int o = 0; o < 8; ++o) {
        const int oc = ocg * 8 + o;
        const float biS = bs[oc];
        const float biE = bE[oc];
        float4 v;
        v.x = silu_f(accS[o][0] + biS) + gate * silu_f(accE[o][0] + biE);
        v.y = silu_f(accS[o][1] + biS) + gate * silu_f(accE[o][1] + biE);
        v.z = silu_f(accS[o][2] + biS) + gate * silu_f(accE[o][2] + biE);
        v.w = silu_f(accS[o][3] + biS) + gate * silu_f(accE[o][3] + biE);
        *(float4*)(g_moe + ((size_t)b * 128 + oc) * HWn + (y0 + r) * Wn + x0 + 4 * s) = v;
    }
}

// ---------------------------------------------------------------------------
// launch
// ---------------------------------------------------------------------------
extern "C" void kernel_launch(void* const* d_in, const int* in_sizes, int n_in,
                              void* d_out, int out_size)
{
    const float* x  = (const float*)d_in[0];
    const float* w1 = (const float*)d_in[1];
    const float* b1 = (const float*)d_in[2];
    const float* wr = (const float*)d_in[3];
    const float* br = (const float*)d_in[4];
    const float* ws = (const float*)d_in[5];
    const float* bs = (const float*)d_in[6];
    const float* we = (const float*)d_in[7];
    const float* be = (const float*)d_in[8];
    const float* w2 = (const float*)d_in[9];
    const float* b2 = (const float*)d_in[10];
    float* out = (float*)d_out;

    // 1) t = silu(conv1x1(x, w1, b1))   [writes g_t]
    conv1x1_silu_k<256, false, true><<<dim3(HWn / 128, 2, Bn), 256>>>(x, w1, b1, nullptr);

    // 2) pooled = mean(feat)
    pool_k<<<dim3(CHn, Bn), 256>>>();

    // 3) routing: top-1 expert + gate
    route_k<<<1, 32>>>(wr, br);

    // 4) moe_out = silu(shared conv) + gate * silu(expert conv)   [writes g_moe]
    conv3x3_moe_k<<<dim3(10, 16, Bn), 160>>>(ws, bs, we, be);

    // 5) out = silu(conv1x1(cat[a, feat, moe], w2, b2))
    conv1x1_silu_k<384, true, false><<<dim3(HWn / 128, 2, Bn), 256>>>(nullptr, w2, b2, out);
}

// round 5
// speedup vs baseline: 1.0189x; 1.0189x over previous
#include <cuda_runtime.h>
#include <math.h>

// Problem constants
#define Bn   32
#define C1n  256
#define CHn  128
#define Hn   80
#define Wn   80
#define HWn  6400
#define NRn  3

// ---------------------------------------------------------------------------
// Scratch (device globals: allocation-free per harness rules)
// ---------------------------------------------------------------------------
__device__ float g_t  [Bn * C1n * HWn];   // t = silu(conv1(x)) : [B,256,HW]
__device__ float g_moe[Bn * CHn * HWn];   // moe_out            : [B,128,HW]
__device__ float g_pooled[Bn * CHn];
__device__ int   g_eidx[Bn];
__device__ float g_egate[Bn];

__device__ __forceinline__ float silu_f(float v) {
    return v * (1.0f / (1.0f + __expf(-v)));
}

// ---------------------------------------------------------------------------
// Kernel 1/5: 1x1 conv (GEMM) + bias + SiLU  (proven Round-2 form)
// Tile: 128 px x 128 oc per block, 256 threads, each thread 8 px x 8 oc.
// ---------------------------------------------------------------------------
template<int KVAL, bool FROM_CAT, bool WRITE_T>
__global__ __launch_bounds__(256) void conv1x1_silu_k(
    const float* __restrict__ xin,
    const float* __restrict__ w,       // [256, KVAL]
    const float* __restrict__ bias,    // [256]
    float* __restrict__ outp)
{
    __shared__ float xs [8][128];
    __shared__ float wsm[8][128];

    const int b   = blockIdx.z;
    const int ocB = blockIdx.y * 128;
    const int p0  = blockIdx.x * 128;
    const int tid = threadIdx.x;
    const int pxs = tid & 15;   // pixel strip 0..15 (8 px each)
    const int ocg = tid >> 4;   // oc group 0..15 (8 oc each)

    float acc[8][8];
#pragma unroll
    for (int i = 0; i < 8; ++i)
#pragma unroll
        for (int j = 0; j < 8; ++j) acc[i][j] = 0.0f;

    const int li_c  = tid >> 5;        // 0..7
    const int li_f  = tid & 31;        // float4 idx in 128-px row
    const int wi_oc = tid >> 1;        // 0..127
    const int wi_i4 = (tid & 1) * 4;

    for (int ic0 = 0; ic0 < KVAL; ic0 += 8) {
        const int c = ic0 + li_c;
        const float* srow;
        if (FROM_CAT) {
            srow = (c < 256) ? (g_t   + ((size_t)b * 256 + c)        * HWn)
                             : (g_moe + ((size_t)b * 128 + (c - 256)) * HWn);
        } else {
            srow = xin + ((size_t)b * 256 + c) * HWn;
        }
        *(float4*)(&xs[li_c][li_f * 4]) = *(const float4*)(srow + p0 + li_f * 4);

        float4 wv = *(const float4*)(w + (size_t)(ocB + wi_oc) * KVAL + ic0 + wi_i4);
        wsm[wi_i4 + 0][wi_oc] = wv.x;
        wsm[wi_i4 + 1][wi_oc] = wv.y;
        wsm[wi_i4 + 2][wi_oc] = wv.z;
        wsm[wi_i4 + 3][wi_oc] = wv.w;
        __syncthreads();

#pragma unroll
        for (int ic = 0; ic < 8; ++ic) {
            float xr[8], wr_[8];
            *(float4*)&xr [0] = *(const float4*)&xs [ic][pxs * 8];
            *(float4*)&xr [4] = *(const float4*)&xs [ic][pxs * 8 + 4];
            *(float4*)&wr_[0] = *(const float4*)&wsm[ic][ocg * 8];
            *(float4*)&wr_[4] = *(const float4*)&wsm[ic][ocg * 8 + 4];
#pragma unroll
            for (int i = 0; i < 8; ++i)
#pragma unroll
                for (int j = 0; j < 8; ++j)
                    acc[i][j] += wr_[i] * xr[j];
        }
        __syncthreads();
    }

    float* dstbase = WRITE_T ? g_t : outp;
#pragma unroll
    for (int i = 0; i < 8; ++i) {
        const int oc = ocB + ocg * 8 + i;
        const float bi = bias[oc];
        float* orow = dstbase + ((size_t)b * 256 + oc) * HWn + p0 + pxs * 8;
        float4 v0, v1;
        v0.x = silu_f(acc[i][0] + bi);
        v0.y = silu_f(acc[i][1] + bi);
        v0.z = silu_f(acc[i][2] + bi);
        v0.w = silu_f(acc[i][3] + bi);
        v1.x = silu_f(acc[i][4] + bi);
        v1.y = silu_f(acc[i][5] + bi);
        v1.z = silu_f(acc[i][6] + bi);
        v1.w = silu_f(acc[i][7] + bi);
        *(float4*)(orow)     = v0;
        *(float4*)(orow + 4) = v1;
    }
}

// ---------------------------------------------------------------------------
// Kernel 2: global average pool of feat -> g_pooled
// ---------------------------------------------------------------------------
__global__ __launch_bounds__(256) void pool_k()
{
    const int c = blockIdx.x;
    const int b = blockIdx.y;
    const float* row = g_t + ((size_t)b * 256 + 128 + c) * HWn;
    float sum = 0.0f;
    for (int i = threadIdx.x; i < HWn / 4; i += 256) {
        float4 v = ((const float4*)row)[i];
        sum += v.x + v.y + v.z + v.w;
    }
    __shared__ float sred[8];
#pragma unroll
    for (int off = 16; off; off >>= 1)
        sum += __shfl_down_sync(0xffffffffu, sum, off);
    if ((threadIdx.x & 31) == 0) sred[threadIdx.x >> 5] = sum;
    __syncthreads();
    if (threadIdx.x < 8) {
        float v = sred[threadIdx.x];
#pragma unroll
        for (int off = 4; off; off >>= 1)
            v += __shfl_down_sync(0xffu, v, off);
        if (threadIdx.x == 0)
            g_pooled[b * 128 + c] = v * (1.0f / (float)HWn);
    }
}

// ---------------------------------------------------------------------------
// Kernel 3: routing (softmax over 3 logits, top-1)
// ---------------------------------------------------------------------------
__global__ void route_k(const float* __restrict__ wr, const float* __restrict__ br)
{
    const int b = threadIdx.x;
    if (b >= Bn) return;
    float lg[NRn];
#pragma unroll
    for (int e = 0; e < NRn; ++e) lg[e] = br[e];
    for (int c = 0; c < CHn; ++c) {
        const float p = g_pooled[b * 128 + c];
        lg[0] += p * wr[c * NRn + 0];
        lg[1] += p * wr[c * NRn + 1];
        lg[2] += p * wr[c * NRn + 2];
    }
    int best = 0;
    float m = lg[0];
    if (lg[1] > m) { m = lg[1]; best = 1; }   // strict > keeps lowest index on ties
    if (lg[2] > m) { m = lg[2]; best = 2; }
    const float s = expf(lg[0] - m) + expf(lg[1] - m) + expf(lg[2] - m);
    g_eidx[b]  = best;
    g_egate[b] = 1.0f / s;
}

// ---------------------------------------------------------------------------
// Kernel 4: fused 3x3 convs, scalar FFMA, vectorized smem reads.
//   moe = silu(conv(feat, ws)+bs) + gate*silu(conv(feat, we[e])+be[e])
// Tile: 40(W) x 16(H) x 8 oc, 160 threads; per thread 4 px x 8 oc x 2 convs.
// Weights staged tap-major [72][8] so each (tap,conv) fetch is 2x LDS.128
// broadcast; input rows 16B-aligned (stride 44) -> LDS.128 + LDS.64.
// ---------------------------------------------------------------------------
__global__ __launch_bounds__(160) void conv3x3_moe_k(
    const float* __restrict__ ws, const float* __restrict__ bs,
    const float* __restrict__ we, const float* __restrict__ be)
{
    __shared__ float sIn[8][18][44];    // pad 42->44: 16B-aligned rows
    __shared__ float sWS[72][8];        // [ic*9+tap][oc]  (oc contiguous)
    __shared__ float sWE[72][8];

    const int b   = blockIdx.z;
    const int ocg = blockIdx.y;             // 0..15
    const int bx  = blockIdx.x;             // 0..9
    const int x0  = (bx & 1) * 40;
    const int y0  = (bx >> 1) * 16;
    const int tid = threadIdx.x;
    const int r   = tid / 10;               // 0..15
    const int s   = tid % 10;               // 0..9

    const int   e    = g_eidx[b];
    const float gate = g_egate[b];
    const float* feat = g_t + ((size_t)b * 256 + 128) * HWn;
    const float* wE   = we + (size_t)e * CHn * CHn * 9;
    const float* bE   = be + e * CHn;

    float accS[8][4], accE[8][4];
#pragma unroll
    for (int o = 0; o < 8; ++o)
#pragma unroll
        for (int p = 0; p < 4; ++p) { accS[o][p] = 0.0f; accE[o][p] = 0.0f; }

    for (int ic0 = 0; ic0 < CHn; ic0 += 8) {
        // ---- stage input tile (zero halo) ----
        for (int j = tid; j < 18 * 42; j += 160) {
            const int rr = j / 42, cc = j % 42;
            const int gy = y0 - 1 + rr, gx = x0 - 1 + cc;
            const bool ok = ((unsigned)gy < (unsigned)Hn) && ((unsigned)gx < (unsigned)Wn);
            const int  gofs = gy * Wn + gx;
            const float* fbase = feat + (size_t)ic0 * HWn + gofs;
#pragma unroll
            for (int i = 0; i < 8; ++i) {
                float v = 0.0f;
                if (ok) v = fbase[(size_t)i * HWn];
                sIn[i][rr][cc] = v;
            }
        }
        // ---- stage weights tap-major (coalesced global reads) ----
        for (int j = tid; j < 8 * 72; j += 160) {
            const int oc = j / 72, t = j % 72;
            sWS[t][oc] = ws[(size_t)(ocg * 8 + oc) * (CHn * 9) + ic0 * 9 + t];
            sWE[t][oc] = wE[(size_t)(ocg * 8 + oc) * (CHn * 9) + ic0 * 9 + t];
        }
        __syncthreads();

#pragma unroll 2
        for (int ic = 0; ic < 8; ++ic) {
#pragma unroll
            for (int ky = 0; ky < 3; ++ky) {
                const float* rowp = &sIn[ic][r + ky][4 * s];   // 16B-aligned
                float4 ia = *(const float4*)rowp;              // cols 4s..4s+3
                float2 ib = *(const float2*)(rowp + 4);        // cols 4s+4..4s+5
                float in6[6] = { ia.x, ia.y, ia.z, ia.w, ib.x, ib.y };
#pragma unroll
                for (int kx = 0; kx < 3; ++kx) {
                    const int t = ic * 9 + ky * 3 + kx;
                    // broadcast LDS.128 x2 per conv
                    float4 wsa = *(const float4*)&sWS[t][0];
                    float4 wsb = *(const float4*)&sWS[t][4];
                    float4 wea = *(const float4*)&sWE[t][0];
                    float4 web = *(const float4*)&sWE[t][4];
                    float wS8[8] = { wsa.x, wsa.y, wsa.z, wsa.w,
                                     wsb.x, wsb.y, wsb.z, wsb.w };
                    float wE8[8] = { wea.x, wea.y, wea.z, wea.w,
                                     web.x, web.y, web.z, web.w };
#pragma unroll
                    for (int o = 0; o < 8; ++o)
#pragma unroll
                        for (int px = 0; px < 4; ++px) {
                            accS[o][px] += in6[px + kx] * wS8[o];
                            accE[o][px] += in6[px + kx] * wE8[o];
                        }
                }
            }
        }
        __syncthreads();
    }

#pragma unroll
    for (int o = 0; o < 8; ++o) {
        const int oc = ocg * 8 + o;
        const float biS = bs[oc];
        const float biE = bE[oc];
        float4 v;
        v.x = silu_f(accS[o][0] + biS) + gate * silu_f(accE[o][0] + biE);
        v.y = silu_f(accS[o][1] + biS) + gate * silu_f(accE[o][1] + biE);
        v.z = silu_f(accS[o][2] + biS) + gate * silu_f(accE[o][2] + biE);
        v.w = silu_f(accS[o][3] + biS) + gate * silu_f(accE[o][3] + biE);
        *(float4*)(g_moe + ((size_t)b * 128 + oc) * HWn + (y0 + r) * Wn + x0 + 4 * s) = v;
    }
}

// ---------------------------------------------------------------------------
// launch
// ---------------------------------------------------------------------------
extern "C" void kernel_launch(void* const* d_in, const int* in_sizes, int n_in,
                              void* d_out, int out_size)
{
    const float* x  = (const float*)d_in[0];
    const float* w1 = (const float*)d_in[1];
    const float* b1 = (const float*)d_in[2];
    const float* wr = (const float*)d_in[3];
    const float* br = (const float*)d_in[4];
    const float* ws = (const float*)d_in[5];
    const float* bs = (const float*)d_in[6];
    const float* we = (const float*)d_in[7];
    const float* be = (const float*)d_in[8];
    const float* w2 = (const float*)d_in[9];
    const float* b2 = (const float*)d_in[10];
    float* out = (float*)d_out;

    conv1x1_silu_k<256, false, true><<<dim3(HWn / 128, 2, Bn), 256>>>(x, w1, b1, nullptr);
    pool_k<<<dim3(CHn, Bn), 256>>>();
    route_k<<<1, 32>>>(wr, br);
    conv3x3_moe_k<<<dim3(10, 16, Bn), 160>>>(ws, bs, we, be);
    conv1x1_silu_k<384, true, false><<<dim3(HWn / 128, 2, Bn), 256>>>(nullptr, w2, b2, out);
}

// round 7
// speedup vs baseline: 1.0409x; 1.0215x over previous
#include <cuda_runtime.h>
#include <math.h>

// Problem constants
#define Bn   32
#define C1n  256
#define CHn  128
#define Hn   80
#define Wn   80
#define HWn  6400
#define NRn  3

// ---------------------------------------------------------------------------
// Scratch (device globals: allocation-free per harness rules)
// ---------------------------------------------------------------------------
__device__ float g_t  [Bn * C1n * HWn];   // t = silu(conv1(x)) : [B,256,HW]
__device__ float g_moe[Bn * CHn * HWn];   // moe_out            : [B,128,HW]
__device__ float g_pooled[Bn * CHn];
__device__ int   g_eidx[Bn];
__device__ float g_egate[Bn];

__device__ __forceinline__ float silu_f(float v) {
    return v * (1.0f / (1.0f + __expf(-v)));
}

// ---------------------------------------------------------------------------
// Kernel 1/5: 1x1 conv (GEMM) + bias + SiLU  (proven Round-2 form)
// Tile: 128 px x 128 oc per block, 256 threads, each thread 8 px x 8 oc.
// ---------------------------------------------------------------------------
template<int KVAL, bool FROM_CAT, bool WRITE_T>
__global__ __launch_bounds__(256) void conv1x1_silu_k(
    const float* __restrict__ xin,
    const float* __restrict__ w,       // [256, KVAL]
    const float* __restrict__ bias,    // [256]
    float* __restrict__ outp)
{
    __shared__ float xs [8][128];
    __shared__ float wsm[8][128];

    const int b   = blockIdx.z;
    const int ocB = blockIdx.y * 128;
    const int p0  = blockIdx.x * 128;
    const int tid = threadIdx.x;
    const int pxs = tid & 15;   // pixel strip 0..15 (8 px each)
    const int ocg = tid >> 4;   // oc group 0..15 (8 oc each)

    float acc[8][8];
#pragma unroll
    for (int i = 0; i < 8; ++i)
#pragma unroll
        for (int j = 0; j < 8; ++j) acc[i][j] = 0.0f;

    const int li_c  = tid >> 5;        // 0..7
    const int li_f  = tid & 31;        // float4 idx in 128-px row
    const int wi_oc = tid >> 1;        // 0..127
    const int wi_i4 = (tid & 1) * 4;

    for (int ic0 = 0; ic0 < KVAL; ic0 += 8) {
        const int c = ic0 + li_c;
        const float* srow;
        if (FROM_CAT) {
            srow = (c < 256) ? (g_t   + ((size_t)b * 256 + c)        * HWn)
                             : (g_moe + ((size_t)b * 128 + (c - 256)) * HWn);
        } else {
            srow = xin + ((size_t)b * 256 + c) * HWn;
        }
        *(float4*)(&xs[li_c][li_f * 4]) = *(const float4*)(srow + p0 + li_f * 4);

        float4 wv = *(const float4*)(w + (size_t)(ocB + wi_oc) * KVAL + ic0 + wi_i4);
        wsm[wi_i4 + 0][wi_oc] = wv.x;
        wsm[wi_i4 + 1][wi_oc] = wv.y;
        wsm[wi_i4 + 2][wi_oc] = wv.z;
        wsm[wi_i4 + 3][wi_oc] = wv.w;
        __syncthreads();

#pragma unroll
        for (int ic = 0; ic < 8; ++ic) {
            float xr[8], wr_[8];
            *(float4*)&xr [0] = *(const float4*)&xs [ic][pxs * 8];
            *(float4*)&xr [4] = *(const float4*)&xs [ic][pxs * 8 + 4];
            *(float4*)&wr_[0] = *(const float4*)&wsm[ic][ocg * 8];
            *(float4*)&wr_[4] = *(const float4*)&wsm[ic][ocg * 8 + 4];
#pragma unroll
            for (int i = 0; i < 8; ++i)
#pragma unroll
                for (int j = 0; j < 8; ++j)
                    acc[i][j] += wr_[i] * xr[j];
        }
        __syncthreads();
    }

    float* dstbase = WRITE_T ? g_t : outp;
#pragma unroll
    for (int i = 0; i < 8; ++i) {
        const int oc = ocB + ocg * 8 + i;
        const float bi = bias[oc];
        float* orow = dstbase + ((size_t)b * 256 + oc) * HWn + p0 + pxs * 8;
        float4 v0, v1;
        v0.x = silu_f(acc[i][0] + bi);
        v0.y = silu_f(acc[i][1] + bi);
        v0.z = silu_f(acc[i][2] + bi);
        v0.w = silu_f(acc[i][3] + bi);
        v1.x = silu_f(acc[i][4] + bi);
        v1.y = silu_f(acc[i][5] + bi);
        v1.z = silu_f(acc[i][6] + bi);
        v1.w = silu_f(acc[i][7] + bi);
        *(float4*)(orow)     = v0;
        *(float4*)(orow + 4) = v1;
    }
}

// ---------------------------------------------------------------------------
// Kernel 2: global average pool of feat -> g_pooled
// ---------------------------------------------------------------------------
__global__ __launch_bounds__(256) void pool_k()
{
    const int c = blockIdx.x;
    const int b = blockIdx.y;
    const float* row = g_t + ((size_t)b * 256 + 128 + c) * HWn;
    float sum = 0.0f;
    for (int i = threadIdx.x; i < HWn / 4; i += 256) {
        float4 v = ((const float4*)row)[i];
        sum += v.x + v.y + v.z + v.w;
    }
    __shared__ float sred[8];
#pragma unroll
    for (int off = 16; off; off >>= 1)
        sum += __shfl_down_sync(0xffffffffu, sum, off);
    if ((threadIdx.x & 31) == 0) sred[threadIdx.x >> 5] = sum;
    __syncthreads();
    if (threadIdx.x < 8) {
        float v = sred[threadIdx.x];
#pragma unroll
        for (int off = 4; off; off >>= 1)
            v += __shfl_down_sync(0xffu, v, off);
        if (threadIdx.x == 0)
            g_pooled[b * 128 + c] = v * (1.0f / (float)HWn);
    }
}

// ---------------------------------------------------------------------------
// Kernel 3: routing (softmax over 3 logits, top-1)
// ---------------------------------------------------------------------------
__global__ void route_k(const float* __restrict__ wr, const float* __restrict__ br)
{
    const int b = threadIdx.x;
    if (b >= Bn) return;
    float lg[NRn];
#pragma unroll
    for (int e = 0; e < NRn; ++e) lg[e] = br[e];
    for (int c = 0; c < CHn; ++c) {
        const float p = g_pooled[b * 128 + c];
        lg[0] += p * wr[c * NRn + 0];
        lg[1] += p * wr[c * NRn + 1];
        lg[2] += p * wr[c * NRn + 2];
    }
    int best = 0;
    float m = lg[0];
    if (lg[1] > m) { m = lg[1]; best = 1; }   // strict > keeps lowest index on ties
    if (lg[2] > m) { m = lg[2]; best = 2; }
    const float s = expf(lg[0] - m) + expf(lg[1] - m) + expf(lg[2] - m);
    g_eidx[b]  = best;
    g_egate[b] = 1.0f / s;
}

// ---------------------------------------------------------------------------
// Kernel 4: fused 3x3 convs, scalar FFMA, vectorized smem reads,
// register-capped to restore 4 blocks/SM (occupancy fix).
//   moe = silu(conv(feat, ws)+bs) + gate*silu(conv(feat, we[e])+be[e])
// Tile: 40(W) x 16(H) x 8 oc, 160 threads; per thread 4 px x 8 oc x 2 convs.
// ---------------------------------------------------------------------------
__global__ __launch_bounds__(160, 4) void conv3x3_moe_k(
    const float* __restrict__ ws, const float* __restrict__ bs,
    const float* __restrict__ we, const float* __restrict__ be)
{
    __shared__ float sIn[8][18][44];    // pad 42->44: 16B-aligned rows
    __shared__ float sWS[72][8];        // [ic*9+tap][oc]  (oc contiguous)
    __shared__ float sWE[72][8];

    const int b   = blockIdx.z;
    const int ocg = blockIdx.y;             // 0..15
    const int bx  = blockIdx.x;             // 0..9
    const int x0  = (bx & 1) * 40;
    const int y0  = (bx >> 1) * 16;
    const int tid = threadIdx.x;
    const int r   = tid / 10;               // 0..15
    const int s   = tid % 10;               // 0..9

    const int   e    = g_eidx[b];
    const float gate = g_egate[b];
    const float* feat = g_t + ((size_t)b * 256 + 128) * HWn;
    const float* wE   = we + (size_t)e * CHn * CHn * 9;
    const float* bE   = be + e * CHn;

    float accS[8][4], accE[8][4];
#pragma unroll
    for (int o = 0; o < 8; ++o)
#pragma unroll
        for (int p = 0; p < 4; ++p) { accS[o][p] = 0.0f; accE[o][p] = 0.0f; }

    for (int ic0 = 0; ic0 < CHn; ic0 += 8) {
        // ---- stage input tile (zero halo) ----
        for (int j = tid; j < 18 * 42; j += 160) {
            const int rr = j / 42, cc = j % 42;
            const int gy = y0 - 1 + rr, gx = x0 - 1 + cc;
            const bool ok = ((unsigned)gy < (unsigned)Hn) && ((unsigned)gx < (unsigned)Wn);
            const int  gofs = gy * Wn + gx;
            const float* fbase = feat + (size_t)ic0 * HWn + gofs;
#pragma unroll
            for (int i = 0; i < 8; ++i) {
                float v = 0.0f;
                if (ok) v = fbase[(size_t)i * HWn];
                sIn[i][rr][cc] = v;
            }
        }
        // ---- stage weights tap-major (coalesced global reads) ----
        for (int j = tid; j < 8 * 72; j += 160) {
            const int oc = j / 72, t = j % 72;
            sWS[t][oc] = ws[(size_t)(ocg * 8 + oc) * (CHn * 9) + ic0 * 9 + t];
            sWE[t][oc] = wE[(size_t)(ocg * 8 + oc) * (CHn * 9) + ic0 * 9 + t];
        }
        __syncthreads();

#pragma unroll 2
        for (int ic = 0; ic < 8; ++ic) {
#pragma unroll
            for (int ky = 0; ky < 3; ++ky) {
                const float* rowp = &sIn[ic][r + ky][4 * s];   // 16B-aligned
                float4 ia = *(const float4*)rowp;              // cols 4s..4s+3
                float2 ib = *(const float2*)(rowp + 4);        // cols 4s+4..4s+5
                float in6[6] = { ia.x, ia.y, ia.z, ia.w, ib.x, ib.y };
#pragma unroll
                for (int kx = 0; kx < 3; ++kx) {
                    const int t = ic * 9 + ky * 3 + kx;
                    // broadcast LDS.128 x2 per conv
                    float4 wsa = *(const float4*)&sWS[t][0];
                    float4 wsb = *(const float4*)&sWS[t][4];
                    float4 wea = *(const float4*)&sWE[t][0];
                    float4 web = *(const float4*)&sWE[t][4];
                    float wS8[8] = { wsa.x, wsa.y, wsa.z, wsa.w,
                                     wsb.x, wsb.y, wsb.z, wsb.w };
                    float wE8[8] = { wea.x, wea.y, wea.z, wea.w,
                                     web.x, web.y, web.z, web.w };
#pragma unroll
                    for (int o = 0; o < 8; ++o)
#pragma unroll
                        for (int px = 0; px < 4; ++px) {
                            accS[o][px] += in6[px + kx] * wS8[o];
                            accE[o][px] += in6[px + kx] * wE8[o];
                        }
                }
            }
        }
        __syncthreads();
    }

#pragma unroll
    for (int o = 0; o < 8; ++o) {
        const int oc = ocg * 8 + o;
        const float biS = bs[oc];
        const float biE = bE[oc];
        float4 v;
        v.x = silu_f(accS[o][0] + biS) + gate * silu_f(accE[o][0] + biE);
        v.y = silu_f(accS[o][1] + biS) + gate * silu_f(accE[o][1] + biE);
        v.z = silu_f(accS[o][2] + biS) + gate * silu_f(accE[o][2] + biE);
        v.w = silu_f(accS[o][3] + biS) + gate * silu_f(accE[o][3] + biE);
        *(float4*)(g_moe + ((size_t)b * 128 + oc) * HWn + (y0 + r) * Wn + x0 + 4 * s) = v;
    }
}

// ---------------------------------------------------------------------------
// launch
// ---------------------------------------------------------------------------
extern "C" void kernel_launch(void* const* d_in, const int* in_sizes, int n_in,
                              void* d_out, int out_size)
{
    const float* x  = (const float*)d_in[0];
    const float* w1 = (const float*)d_in[1];
    const float* b1 = (const float*)d_in[2];
    const float* wr = (const float*)d_in[3];
    const float* br = (const float*)d_in[4];
    const float* ws = (const float*)d_in[5];
    const float* bs = (const float*)d_in[6];
    const float* we = (const float*)d_in[7];
    const float* be = (const float*)d_in[8];
    const float* w2 = (const float*)d_in[9];
    const float* b2 = (const float*)d_in[10];
    float* out = (float*)d_out;

    conv1x1_silu_k<256, false, true><<<dim3(HWn / 128, 2, Bn), 256>>>(x, w1, b1, nullptr);
    pool_k<<<dim3(CHn, Bn), 256>>>();
    route_k<<<1, 32>>>(wr, br);
    conv3x3_moe_k<<<dim3(10, 16, Bn), 160>>>(ws, bs, we, be);
    conv1x1_silu_k<384, true, false><<<dim3(HWn / 128, 2, Bn), 256>>>(nullptr, w2, b2, out);
}

// round 8
// speedup vs baseline: 1.0414x; 1.0005x over previous
#include <cuda_runtime.h>
#include <math.h>

// Problem constants
#define Bn   32
#define C1n  256
#define CHn  128
#define Hn   80
#define Wn   80
#define HWn  6400
#define NRn  3

// ---------------------------------------------------------------------------
// Scratch (device globals: allocation-free per harness rules)
// ---------------------------------------------------------------------------
__device__ float g_t  [Bn * C1n * HWn];   // t = silu(conv1(x)) : [B,256,HW]
__device__ float g_moe[Bn * CHn * HWn];   // moe_out            : [B,128,HW]
__device__ float g_pooled[Bn * CHn];
__device__ int   g_eidx[Bn];
__device__ float g_egate[Bn];

__device__ __forceinline__ float silu_f(float v) {
    return v * (1.0f / (1.0f + __expf(-v)));
}

// ---------------------------------------------------------------------------
// Kernel 1/5: 1x1 conv (GEMM) + bias + SiLU  (proven Round-2 form)
// Tile: 128 px x 128 oc per block, 256 threads, each thread 8 px x 8 oc.
// ---------------------------------------------------------------------------
template<int KVAL, bool FROM_CAT, bool WRITE_T>
__global__ __launch_bounds__(256) void conv1x1_silu_k(
    const float* __restrict__ xin,
    const float* __restrict__ w,       // [256, KVAL]
    const float* __restrict__ bias,    // [256]
    float* __restrict__ outp)
{
    __shared__ float xs [8][128];
    __shared__ float wsm[8][128];

    const int b   = blockIdx.z;
    const int ocB = blockIdx.y * 128;
    const int p0  = blockIdx.x * 128;
    const int tid = threadIdx.x;
    const int pxs = tid & 15;   // pixel strip 0..15 (8 px each)
    const int ocg = tid >> 4;   // oc group 0..15 (8 oc each)

    float acc[8][8];
#pragma unroll
    for (int i = 0; i < 8; ++i)
#pragma unroll
        for (int j = 0; j < 8; ++j) acc[i][j] = 0.0f;

    const int li_c  = tid >> 5;        // 0..7
    const int li_f  = tid & 31;        // float4 idx in 128-px row
    const int wi_oc = tid >> 1;        // 0..127
    const int wi_i4 = (tid & 1) * 4;

    for (int ic0 = 0; ic0 < KVAL; ic0 += 8) {
        const int c = ic0 + li_c;
        const float* srow;
        if (FROM_CAT) {
            srow = (c < 256) ? (g_t   + ((size_t)b * 256 + c)        * HWn)
                             : (g_moe + ((size_t)b * 128 + (c - 256)) * HWn);
        } else {
            srow = xin + ((size_t)b * 256 + c) * HWn;
        }
        *(float4*)(&xs[li_c][li_f * 4]) = *(const float4*)(srow + p0 + li_f * 4);

        float4 wv = *(const float4*)(w + (size_t)(ocB + wi_oc) * KVAL + ic0 + wi_i4);
        wsm[wi_i4 + 0][wi_oc] = wv.x;
        wsm[wi_i4 + 1][wi_oc] = wv.y;
        wsm[wi_i4 + 2][wi_oc] = wv.z;
        wsm[wi_i4 + 3][wi_oc] = wv.w;
        __syncthreads();

#pragma unroll
        for (int ic = 0; ic < 8; ++ic) {
            float xr[8], wr_[8];
            *(float4*)&xr [0] = *(const float4*)&xs [ic][pxs * 8];
            *(float4*)&xr [4] = *(const float4*)&xs [ic][pxs * 8 + 4];
            *(float4*)&wr_[0] = *(const float4*)&wsm[ic][ocg * 8];
            *(float4*)&wr_[4] = *(const float4*)&wsm[ic][ocg * 8 + 4];
#pragma unroll
            for (int i = 0; i < 8; ++i)
#pragma unroll
                for (int j = 0; j < 8; ++j)
                    acc[i][j] += wr_[i] * xr[j];
        }
        __syncthreads();
    }

    float* dstbase = WRITE_T ? g_t : outp;
#pragma unroll
    for (int i = 0; i < 8; ++i) {
        const int oc = ocB + ocg * 8 + i;
        const float bi = bias[oc];
        float* orow = dstbase + ((size_t)b * 256 + oc) * HWn + p0 + pxs * 8;
        float4 v0, v1;
        v0.x = silu_f(acc[i][0] + bi);
        v0.y = silu_f(acc[i][1] + bi);
        v0.z = silu_f(acc[i][2] + bi);
        v0.w = silu_f(acc[i][3] + bi);
        v1.x = silu_f(acc[i][4] + bi);
        v1.y = silu_f(acc[i][5] + bi);
        v1.z = silu_f(acc[i][6] + bi);
        v1.w = silu_f(acc[i][7] + bi);
        *(float4*)(orow)     = v0;
        *(float4*)(orow + 4) = v1;
    }
}

// ---------------------------------------------------------------------------
// Kernel 2: global average pool of feat -> g_pooled
// ---------------------------------------------------------------------------
__global__ __launch_bounds__(256) void pool_k()
{
    const int c = blockIdx.x;
    const int b = blockIdx.y;
    const float* row = g_t + ((size_t)b * 256 + 128 + c) * HWn;
    float sum = 0.0f;
    for (int i = threadIdx.x; i < HWn / 4; i += 256) {
        float4 v = ((const float4*)row)[i];
        sum += v.x + v.y + v.z + v.w;
    }
    __shared__ float sred[8];
#pragma unroll
    for (int off = 16; off; off >>= 1)
        sum += __shfl_down_sync(0xffffffffu, sum, off);
    if ((threadIdx.x & 31) == 0) sred[threadIdx.x >> 5] = sum;
    __syncthreads();
    if (threadIdx.x < 8) {
        float v = sred[threadIdx.x];
#pragma unroll
        for (int off = 4; off; off >>= 1)
            v += __shfl_down_sync(0xffu, v, off);
        if (threadIdx.x == 0)
            g_pooled[b * 128 + c] = v * (1.0f / (float)HWn);
    }
}

// ---------------------------------------------------------------------------
// Kernel 3: routing (softmax over 3 logits, top-1)
// ---------------------------------------------------------------------------
__global__ void route_k(const float* __restrict__ wr, const float* __restrict__ br)
{
    const int b = threadIdx.x;
    if (b >= Bn) return;
    float lg[NRn];
#pragma unroll
    for (int e = 0; e < NRn; ++e) lg[e] = br[e];
    for (int c = 0; c < CHn; ++c) {
        const float p = g_pooled[b * 128 + c];
        lg[0] += p * wr[c * NRn + 0];
        lg[1] += p * wr[c * NRn + 1];
        lg[2] += p * wr[c * NRn + 2];
    }
    int best = 0;
    float m = lg[0];
    if (lg[1] > m) { m = lg[1]; best = 1; }   // strict > keeps lowest index on ties
    if (lg[2] > m) { m = lg[2]; best = 2; }
    const float s = expf(lg[0] - m) + expf(lg[1] - m) + expf(lg[2] - m);
    g_eidx[b]  = best;
    g_egate[b] = 1.0f / s;
}

// ---------------------------------------------------------------------------
// Kernel 4: fused 3x3 convs, scalar FFMA, vectorized smem reads,
// register-capped to restore 4 blocks/SM (occupancy fix).
//   moe = silu(conv(feat, ws)+bs) + gate*silu(conv(feat, we[e])+be[e])
// Tile: 40(W) x 16(H) x 8 oc, 160 threads; per thread 4 px x 8 oc x 2 convs.
// ---------------------------------------------------------------------------
__global__ __launch_bounds__(160, 4) void conv3x3_moe_k(
    const float* __restrict__ ws, const float* __restrict__ bs,
    const float* __restrict__ we, const float* __restrict__ be)
{
    __shared__ float sIn[8][18][44];    // pad 42->44: 16B-aligned rows
    __shared__ float sWS[72][8];        // [ic*9+tap][oc]  (oc contiguous)
    __shared__ float sWE[72][8];

    const int b   = blockIdx.z;
    const int ocg = blockIdx.y;             // 0..15
    const int bx  = blockIdx.x;             // 0..9
    const int x0  = (bx & 1) * 40;
    const int y0  = (bx >> 1) * 16;
    const int tid = threadIdx.x;
    const int r   = tid / 10;               // 0..15
    const int s   = tid % 10;               // 0..9

    const int   e    = g_eidx[b];
    const float gate = g_egate[b];
    const float* feat = g_t + ((size_t)b * 256 + 128) * HWn;
    const float* wE   = we + (size_t)e * CHn * CHn * 9;
    const float* bE   = be + e * CHn;

    float accS[8][4], accE[8][4];
#pragma unroll
    for (int o = 0; o < 8; ++o)
#pragma unroll
        for (int p = 0; p < 4; ++p) { accS[o][p] = 0.0f; accE[o][p] = 0.0f; }

    for (int ic0 = 0; ic0 < CHn; ic0 += 8) {
        // ---- stage input tile (zero halo) ----
        for (int j = tid; j < 18 * 42; j += 160) {
            const int rr = j / 42, cc = j % 42;
            const int gy = y0 - 1 + rr, gx = x0 - 1 + cc;
            const bool ok = ((unsigned)gy < (unsigned)Hn) && ((unsigned)gx < (unsigned)Wn);
            const int  gofs = gy * Wn + gx;
            const float* fbase = feat + (size_t)ic0 * HWn + gofs;
#pragma unroll
            for (int i = 0; i < 8; ++i) {
                float v = 0.0f;
                if (ok) v = fbase[(size_t)i * HWn];
                sIn[i][rr][cc] = v;
            }
        }
        // ---- stage weights tap-major (coalesced global reads) ----
        for (int j = tid; j < 8 * 72; j += 160) {
            const int oc = j / 72, t = j % 72;
            sWS[t][oc] = ws[(size_t)(ocg * 8 + oc) * (CHn * 9) + ic0 * 9 + t];
            sWE[t][oc] = wE[(size_t)(ocg * 8 + oc) * (CHn * 9) + ic0 * 9 + t];
        }
        __syncthreads();

#pragma unroll 2
        for (int ic = 0; ic < 8; ++ic) {
#pragma unroll
            for (int ky = 0; ky < 3; ++ky) {
                const float* rowp = &sIn[ic][r + ky][4 * s];   // 16B-aligned
                float4 ia = *(const float4*)rowp;              // cols 4s..4s+3
                float2 ib = *(const float2*)(rowp + 4);        // cols 4s+4..4s+5
                float in6[6] = { ia.x, ia.y, ia.z, ia.w, ib.x, ib.y };
#pragma unroll
                for (int kx = 0; kx < 3; ++kx) {
                    const int t = ic * 9 + ky * 3 + kx;
                    // broadcast LDS.128 x2 per conv
                    float4 wsa = *(const float4*)&sWS[t][0];
                    float4 wsb = *(const float4*)&sWS[t][4];
                    float4 wea = *(const float4*)&sWE[t][0];
                    float4 web = *(const float4*)&sWE[t][4];
                    float wS8[8] = { wsa.x, wsa.y, wsa.z, wsa.w,
                                     wsb.x, wsb.y, wsb.z, wsb.w };
                    float wE8[8] = { wea.x, wea.y, wea.z, wea.w,
                                     web.x, web.y, web.z, web.w };
#pragma unroll
                    for (int o = 0; o < 8; ++o)
#pragma unroll
                        for (int px = 0; px < 4; ++px) {
                            accS[o][px] += in6[px + kx] * wS8[o];
                            accE[o][px] += in6[px + kx] * wE8[o];
                        }
                }
            }
        }
        __syncthreads();
    }

#pragma unroll
    for (int o = 0; o < 8; ++o) {
        const int oc = ocg * 8 + o;
        const float biS = bs[oc];
        const float biE = bE[oc];
        float4 v;
        v.x = silu_f(accS[o][0] + biS) + gate * silu_f(accE[o][0] + biE);
        v.y = silu_f(accS[o][1] + biS) + gate * silu_f(accE[o][1] + biE);
        v.z = silu_f(accS[o][2] + biS) + gate * silu_f(accE[o][2] + biE);
        v.w = silu_f(accS[o][3] + biS) + gate * silu_f(accE[o][3] + biE);
        *(float4*)(g_moe + ((size_t)b * 128 + oc) * HWn + (y0 + r) * Wn + x0 + 4 * s) = v;
    }
}

// ---------------------------------------------------------------------------
// launch
// ---------------------------------------------------------------------------
extern "C" void kernel_launch(void* const* d_in, const int* in_sizes, int n_in,
                              void* d_out, int out_size)
{
    const float* x  = (const float*)d_in[0];
    const float* w1 = (const float*)d_in[1];
    const float* b1 = (const float*)d_in[2];
    const float* wr = (const float*)d_in[3];
    const float* br = (const float*)d_in[4];
    const float* ws = (const float*)d_in[5];
    const float* bs = (const float*)d_in[6];
    const float* we = (const float*)d_in[7];
    const float* be = (const float*)d_in[8];
    const float* w2 = (const float*)d_in[9];
    const float* b2 = (const float*)d_in[10];
    float* out = (float*)d_out;

    conv1x1_silu_k<256, false, true><<<dim3(HWn / 128, 2, Bn), 256>>>(x, w1, b1, nullptr);
    pool_k<<<dim3(CHn, Bn), 256>>>();
    route_k<<<1, 32>>>(wr, br);
    conv3x3_moe_k<<<dim3(10, 16, Bn), 160>>>(ws, bs, we, be);
    conv1x1_silu_k<384, true, false><<<dim3(HWn / 128, 2, Bn), 256>>>(nullptr, w2, b2, out);
}